// round 9
// baseline (speedup 1.0000x reference)
#include <cuda_runtime.h>
#include <math.h>

// Problem constants
#define GRID_SZ 14
#define L_SEQ   197           // 14*14 + 1
#define NH      12
#define DK      64
#define D_MODEL 768
#define BATCH   32
#define M_ROWS  (BATCH * L_SEQ)   // 6304
#define TOPK    32
#define N_ROWS_TOT (BATCH * NH * L_SEQ)  // 75648
#define ATTN_SPLIT 8

typedef unsigned long long u64;

// Scratch (device globals: no allocation allowed)
__device__ float g_Q[M_ROWS * D_MODEL];
__device__ float g_K[M_ROWS * D_MODEL];
__device__ float g_V[M_ROWS * D_MODEL];
__device__ float g_C[M_ROWS * D_MODEL];   // consensus (attention output before W_o)

// ---- packed f32x2 helpers (sm_103a) ---------------------------------------
__device__ __forceinline__ u64 pack2(float x, float y) {
    u64 r;
    asm("mov.b64 %0, {%1, %2};" : "=l"(r) : "f"(x), "f"(y));
    return r;
}
__device__ __forceinline__ void unpack2(u64 v, float& x, float& y) {
    asm("mov.b64 {%0, %1}, %2;" : "=f"(x), "=f"(y) : "l"(v));
}
__device__ __forceinline__ void ffma2(u64& d, u64 a, u64 b) {
    asm("fma.rn.f32x2 %0, %1, %2, %3;" : "=l"(d) : "l"(a), "l"(b), "l"(d));
}

// ---------------------------------------------------------------------------
// SGEMM:  C[M x 768] = A[M x 768] @ B[768 x 768] + bias
// 128x128 tile, BK=8, 256 threads, 8x8 microtile, packed f32x2 FMA,
// DOUBLE-BUFFERED smem (one __syncthreads per k-tile).
// Per-element fmaf chain identical -> bit-identical outputs.
// ---------------------------------------------------------------------------
#define BM 128
#define BN 128
#define BK 8

__global__ __launch_bounds__(256) void sgemm_bias(
    const float* __restrict__ A_ext, int a_sel,
    const float* __restrict__ Bw, const float* __restrict__ bias,
    float* __restrict__ C_ext, int c_sel, int M)
{
    const float* A = (a_sel == 0) ? A_ext : g_C;
    float* C = (c_sel == 0) ? g_Q : (c_sel == 1) ? g_K : (c_sel == 2) ? g_V : C_ext;

    __shared__ __align__(16) float As[2][BK][BM];
    __shared__ __align__(16) float Bs[2][BK][BN];

    int bm = blockIdx.y, bn = blockIdx.x;
    int tid = threadIdx.x;
    int tx = tid & 15;
    int ty = tid >> 4;

    u64 acc2[8][4];
#pragma unroll
    for (int i = 0; i < 8; i++)
#pragma unroll
        for (int j = 0; j < 4; j++) acc2[i][j] = 0ull;

    int row0 = bm * BM;
    int col0 = bn * BN;

    int a_m = (tid * 4) / BK;
    int a_k = (tid * 4) % BK;
    int b_r = (tid * 4) / BN;
    int b_c = (tid * 4) % BN;

    const int gm = row0 + a_m;
    const bool a_ok = (gm < M);
    const float* Aptr = &A[(size_t)gm * D_MODEL + a_k];
    const float* Bptr = &Bw[(size_t)b_r * D_MODEL + col0 + b_c];

    // Load + stage tile 0
    float4 av = make_float4(0.f, 0.f, 0.f, 0.f);
    if (a_ok) av = *reinterpret_cast<const float4*>(Aptr);
    float4 bv = *reinterpret_cast<const float4*>(Bptr);

    As[0][a_k + 0][a_m] = av.x;
    As[0][a_k + 1][a_m] = av.y;
    As[0][a_k + 2][a_m] = av.z;
    As[0][a_k + 3][a_m] = av.w;
    *reinterpret_cast<float4*>(&Bs[0][b_r][b_c]) = bv;
    __syncthreads();

    int cur = 0;
    for (int kt = 0; kt < D_MODEL; kt += BK) {
        const bool has_next = (kt + BK < D_MODEL);
        if (has_next) {
            if (a_ok) av = *reinterpret_cast<const float4*>(Aptr + kt + BK);
            bv = *reinterpret_cast<const float4*>(Bptr + (size_t)(kt + BK) * D_MODEL);
        }

#pragma unroll
        for (int k = 0; k < BK; k++) {
            float ra[8];
            *reinterpret_cast<float4*>(&ra[0]) = *reinterpret_cast<const float4*>(&As[cur][k][ty * 4]);
            *reinterpret_cast<float4*>(&ra[4]) = *reinterpret_cast<const float4*>(&As[cur][k][64 + ty * 4]);

            double2 b01 = *reinterpret_cast<const double2*>(&Bs[cur][k][tx * 4]);
            double2 b23 = *reinterpret_cast<const double2*>(&Bs[cur][k][64 + tx * 4]);
            u64 rb2[4];
            rb2[0] = __double_as_longlong(b01.x);
            rb2[1] = __double_as_longlong(b01.y);
            rb2[2] = __double_as_longlong(b23.x);
            rb2[3] = __double_as_longlong(b23.y);

#pragma unroll
            for (int i = 0; i < 8; i++) {
                u64 ra2 = pack2(ra[i], ra[i]);
#pragma unroll
                for (int j = 0; j < 4; j++)
                    ffma2(acc2[i][j], ra2, rb2[j]);
            }
        }

        if (has_next) {
            int nxt = cur ^ 1;
            As[nxt][a_k + 0][a_m] = av.x;
            As[nxt][a_k + 1][a_m] = av.y;
            As[nxt][a_k + 2][a_m] = av.z;
            As[nxt][a_k + 3][a_m] = av.w;
            *reinterpret_cast<float4*>(&Bs[nxt][b_r][b_c]) = bv;
            __syncthreads();
        }
        cur ^= 1;
    }

#pragma unroll
    for (int i = 0; i < 8; i++) {
        int m = row0 + ((i < 4) ? (ty * 4 + i) : (64 + ty * 4 + (i - 4)));
        if (m >= M) continue;
#pragma unroll
        for (int jj = 0; jj < 4; jj++) {
            float lo, hi;
            unpack2(acc2[i][jj], lo, hi);
            int nbase = col0 + ((jj < 2) ? (tx * 4 + 2 * jj) : (64 + tx * 4 + 2 * (jj - 2)));
            C[(size_t)m * D_MODEL + nbase]     = lo + bias[nbase];
            C[(size_t)m * D_MODEL + nbase + 1] = hi + bias[nbase + 1];
        }
    }
}

// ---------------------------------------------------------------------------
// Attention kernel v4: grid (B*NH, ATTN_SPLIT). K slab transposed in smem.
// i>0 rows: dense row build — invert the box map analytically per output
// column, fetch the weight with one variable-lane shfl, write each dense row
// exactly once (coalesced). Same values at same positions as scatter version.
// i==0 (CLS): unchanged zero-fill + top-32 + scatter path.
// ---------------------------------------------------------------------------
__global__ __launch_bounds__(256) void attn_kernel(
    const float* __restrict__ log_sigma,
    float* __restrict__ w_out, float* __restrict__ m_out)
{
    extern __shared__ float Ks_t[];             // [DK][L_SEQ] transposed K slab
    __shared__ float q_sh[8][DK];
    __shared__ float w_sh[8][32];
    __shared__ int   c_sh[8][32];

    int bh   = blockIdx.x;
    int b    = bh / NH;
    int h    = bh % NH;
    int tid  = threadIdx.x;
    int warp = tid >> 5;
    int lane = tid & 31;

    float inv = -0.5f * expf(-2.f * log_sigma[0]);   // -0.5 / sigma^2

    // Cooperative transposed load of K slab: Ks_t[d * L_SEQ + j] = K[b,h,j,d]
    const float* kslab = g_K + (size_t)b * L_SEQ * D_MODEL + h * DK;
    for (int idx = tid; idx < L_SEQ * DK; idx += 256) {
        int j = idx >> 6;          // 0..196
        int d = idx & 63;          // 0..63
        Ks_t[d * L_SEQ + j] = kslab[(size_t)j * D_MODEL + d];
    }
    __syncthreads();

    const float* vbase = g_V + (size_t)b * L_SEQ * D_MODEL + h * DK;

    for (int i = blockIdx.y * 8 + warp; i < L_SEQ; i += 8 * ATTN_SPLIT) {
        int rowid = (b * NH + h) * L_SEQ + i;

        const float* qp = g_Q + (size_t)(b * L_SEQ + i) * D_MODEL + h * DK;
        q_sh[warp][lane]      = qp[lane];
        q_sh[warp][lane + 32] = qp[lane + 32];
        __syncwarp();

        float* wrow = w_out + (size_t)rowid * L_SEQ;
        float* mrow = m_out + (size_t)rowid * L_SEQ;

        if (i > 0) {
            // lane 0 -> CLS, lanes 1.. -> box cells (Chebyshev<=2)
            int p = i - 1, r = p / GRID_SZ, c = p % GRID_SZ;
            int r0 = (r - 2 < 0) ? 0 : r - 2;
            int r1 = (r + 2 > GRID_SZ - 1) ? GRID_SZ - 1 : r + 2;
            int c0 = (c - 2 < 0) ? 0 : c - 2;
            int c1 = (c + 2 > GRID_SZ - 1) ? GRID_SZ - 1 : c + 2;
            int wbox = c1 - c0 + 1;
            int hbox = r1 - r0 + 1;
            int nj   = 1 + wbox * hbox;
            bool act = lane < nj;

            int j = 0;
            if (act && lane > 0) {
                int idx = lane - 1;
                j = 1 + (r0 + idx / wbox) * GRID_SZ + (c0 + idx % wbox);
            }

            float myScore = -INFINITY;
            if (act) {
                float t[32];
#pragma unroll
                for (int d = 0; d < 32; d++) {
                    float qa = q_sh[warp][d];
                    float ka = Ks_t[d * L_SEQ + j];
                    float qb = q_sh[warp][d + 32];
                    float kb = Ks_t[(d + 32) * L_SEQ + j];
                    float d0 = qa - ka;
                    float d1 = qb - kb;
                    t[d] = fmaf(d1, d1, d0 * d0);
                }
                // butterfly bracketing: offsets 16, 8, 4, 2, 1
#pragma unroll
                for (int off = 16; off > 0; off >>= 1)
#pragma unroll
                    for (int l = 0; l < 16; l++)
                        if (l < off) t[l] += t[l + off];
                myScore = inv * t[0];
            }

            // Softmax over active lanes
            float v  = act ? myScore : -INFINITY;
            float mx = v;
#pragma unroll
            for (int o = 16; o > 0; o >>= 1)
                mx = fmaxf(mx, __shfl_xor_sync(0xffffffffu, mx, o));
            float e  = act ? expf(myScore - mx) : 0.f;
            float se = e;
#pragma unroll
            for (int o = 16; o > 0; o >>= 1)
                se += __shfl_xor_sync(0xffffffffu, se, o);
            float w = e / se;

            // Stash for consensus
            w_sh[warp][lane] = act ? w : 0.f;
            c_sh[warp][lane] = act ? j : 0;
            __syncwarp();

            // Dense row build: for each output column, invert the candidate
            // map and pull the weight from its owner lane.
#pragma unroll
            for (int ss = 0; ss < 7; ss++) {
                int col = ss * 32 + lane;
                int t = -1;
                if (col == 0) {
                    t = 0;
                } else if (col < L_SEQ) {
                    int pp = col - 1;
                    int rr = pp / GRID_SZ;
                    int cc = pp % GRID_SZ;
                    if (rr >= r0 && rr <= r1 && cc >= c0 && cc <= c1)
                        t = 1 + (rr - r0) * wbox + (cc - c0);
                }
                float wv  = __shfl_sync(0xffffffffu, w, (t < 0) ? 0 : t);
                float val = (t >= 0) ? wv : 0.f;
                if (col < L_SEQ) {
                    wrow[col] = val;
                    mrow[col] = (val > 1e-6f) ? 1.f : 0.f;
                }
            }

            // Consensus
            float a0 = 0.f, a1 = 0.f;
#pragma unroll 4
            for (int t = 0; t < nj; t++) {
                float wv  = w_sh[warp][t];
                int   col = c_sh[warp][t];
                const float* vp = vbase + (size_t)col * D_MODEL;
                a0 = fmaf(wv, vp[lane], a0);
                a1 = fmaf(wv, vp[lane + 32], a1);
            }
            float* cp = g_C + (size_t)(b * L_SEQ + i) * D_MODEL + h * DK;
            cp[lane]      = a0;
            cp[lane + 32] = a1;
            __syncwarp();
        } else {
            // CLS row: 197 candidates, true top-32 (lowest-index tie-break)
            float sc[7];
#pragma unroll
            for (int s = 0; s < 7; s++) {
                int j = s * 32 + lane;
                if (j < L_SEQ) {
                    float acc = 0.f;
#pragma unroll
                    for (int d = 0; d < DK; d++) {
                        float df = q_sh[warp][d] - Ks_t[d * L_SEQ + j];
                        acc = fmaf(df, df, acc);
                    }
                    sc[s] = inv * acc;
                } else {
                    sc[s] = -INFINITY;
                }
            }

            float myScore = -INFINITY;
            int   myCol   = 0;
            unsigned used = 0;
            for (int t = 0; t < TOPK; t++) {
                float bv = -INFINITY;
                int   bj = 0x7fffffff;
#pragma unroll
                for (int s = 0; s < 7; s++) {
                    if (!((used >> s) & 1u)) {
                        int j = s * 32 + lane;
                        if (sc[s] > bv || (sc[s] == bv && j < bj)) { bv = sc[s]; bj = j; }
                    }
                }
#pragma unroll
                for (int o = 16; o > 0; o >>= 1) {
                    float ov = __shfl_xor_sync(0xffffffffu, bv, o);
                    int   oj = __shfl_xor_sync(0xffffffffu, bj, o);
                    if (ov > bv || (ov == bv && oj < bj)) { bv = ov; bj = oj; }
                }
                if (lane == (bj & 31)) used |= 1u << (bj >> 5);
                if (lane == t) { myScore = bv; myCol = bj; }
            }

            // Zero-fill dense rows (coalesced)
#pragma unroll
            for (int t = lane; t < L_SEQ; t += 32) { wrow[t] = 0.f; mrow[t] = 0.f; }

            // Softmax over 32 lanes
            float mx = myScore;
#pragma unroll
            for (int o = 16; o > 0; o >>= 1)
                mx = fmaxf(mx, __shfl_xor_sync(0xffffffffu, mx, o));
            float e  = expf(myScore - mx);
            float se = e;
#pragma unroll
            for (int o = 16; o > 0; o >>= 1)
                se += __shfl_xor_sync(0xffffffffu, se, o);
            float w = e / se;

            w_sh[warp][lane] = w;
            c_sh[warp][lane] = myCol;
            __syncwarp();

            wrow[myCol] = w;
            mrow[myCol] = (w > 1e-6f) ? 1.f : 0.f;

            // Consensus
            float a0 = 0.f, a1 = 0.f;
#pragma unroll 4
            for (int t = 0; t < TOPK; t++) {
                float wv  = w_sh[warp][t];
                int   col = c_sh[warp][t];
                const float* vp = vbase + (size_t)col * D_MODEL;
                a0 = fmaf(wv, vp[lane], a0);
                a1 = fmaf(wv, vp[lane + 32], a1);
            }
            float* cp = g_C + (size_t)(b * L_SEQ + i) * D_MODEL + h * DK;
            cp[lane]      = a0;
            cp[lane + 32] = a1;
            __syncwarp();
        }
    }
}

// ---------------------------------------------------------------------------
extern "C" void kernel_launch(void* const* d_in, const int* in_sizes, int n_in,
                              void* d_out, int out_size)
{
    const float* x  = (const float*)d_in[0];
    const float* Wq = (const float*)d_in[1];
    const float* bq = (const float*)d_in[2];
    const float* Wk = (const float*)d_in[3];
    const float* bk = (const float*)d_in[4];
    const float* Wv = (const float*)d_in[5];
    const float* bv = (const float*)d_in[6];
    const float* Wo = (const float*)d_in[7];
    const float* bo = (const float*)d_in[8];
    const float* ls = (const float*)d_in[9];

    float* out   = (float*)d_out;                                    // (B, L, D)
    float* w_out = out + (size_t)M_ROWS * D_MODEL;                   // (B, H, L, L)
    float* m_out = w_out + (size_t)BATCH * NH * L_SEQ * L_SEQ;       // (B, H, L, L)

    dim3 ggrid(D_MODEL / BN, (M_ROWS + BM - 1) / BM);   // (6, 50)
    dim3 gblk(256);

    // QKV projections
    sgemm_bias<<<ggrid, gblk>>>(x, 0, Wq, bq, nullptr, 0, M_ROWS);
    sgemm_bias<<<ggrid, gblk>>>(x, 0, Wk, bk, nullptr, 1, M_ROWS);
    sgemm_bias<<<ggrid, gblk>>>(x, 0, Wv, bv, nullptr, 2, M_ROWS);

    // Attention: grid (B*NH, ATTN_SPLIT), K slab in dynamic smem (50.4 KB)
    const int smem_bytes = L_SEQ * DK * (int)sizeof(float);   // 50432
    cudaFuncSetAttribute(attn_kernel, cudaFuncAttributeMaxDynamicSharedMemorySize,
                         smem_bytes);
    dim3 agrid(BATCH * NH, ATTN_SPLIT);
    attn_kernel<<<agrid, 256, smem_bytes>>>(ls, w_out, m_out);

    // Output projection
    sgemm_bias<<<ggrid, gblk>>>(nullptr, 1, Wo, bo, out, 3, M_ROWS);
}

// round 13
// speedup vs baseline: 1.5825x; 1.5825x over previous
#include <cuda_runtime.h>
#include <cuda_fp16.h>
#include <math.h>

// Problem constants
#define GRID_SZ 14
#define L_SEQ   197           // 14*14 + 1
#define NH      12
#define DK      64
#define D_MODEL 768
#define BATCH   32
#define M_ROWS  (BATCH * L_SEQ)   // 6304
#define TOPK    32
#define N_ROWS_TOT (BATCH * NH * L_SEQ)  // 75648
#define ATTN_SPLIT 4

typedef unsigned int u32;

// Scratch (device globals: no allocation allowed)
__device__ float g_Q[M_ROWS * D_MODEL];
__device__ float g_K[M_ROWS * D_MODEL];
__device__ float g_V[M_ROWS * D_MODEL];
__device__ float g_C[M_ROWS * D_MODEL];   // consensus (pre-W_o)

// fp16 split operands (x = hi + lo; W = hi + lo), W kept [k][n] row-major.
__device__ __half g_Ahi[M_ROWS * D_MODEL];
__device__ __half g_Alo[M_ROWS * D_MODEL];
__device__ __half g_Whi[D_MODEL * D_MODEL];
__device__ __half g_Wlo[D_MODEL * D_MODEL];

// ---- mma.sync / ldmatrix helpers (plain sm_80-era PTX, no 'a' features) ---
__device__ __forceinline__ u32 smem_u32(const void* p) {
    u32 a;
    asm("{ .reg .u64 t; cvta.to.shared.u64 t, %1; cvt.u32.u64 %0, t; }"
        : "=r"(a) : "l"(p));
    return a;
}
__device__ __forceinline__ void ldsm_x4(u32& r0, u32& r1, u32& r2, u32& r3, u32 addr) {
    asm volatile("ldmatrix.sync.aligned.m8n8.x4.shared.b16 {%0,%1,%2,%3}, [%4];"
                 : "=r"(r0), "=r"(r1), "=r"(r2), "=r"(r3) : "r"(addr));
}
__device__ __forceinline__ void ldsm_x4_t(u32& r0, u32& r1, u32& r2, u32& r3, u32 addr) {
    asm volatile("ldmatrix.sync.aligned.m8n8.x4.trans.shared.b16 {%0,%1,%2,%3}, [%4];"
                 : "=r"(r0), "=r"(r1), "=r"(r2), "=r"(r3) : "r"(addr));
}
__device__ __forceinline__ void mma16816(float* c, const u32* a, const u32* b) {
    asm volatile(
        "mma.sync.aligned.m16n8k16.row.col.f32.f16.f16.f32 "
        "{%0,%1,%2,%3}, {%4,%5,%6,%7}, {%8,%9}, {%0,%1,%2,%3};"
        : "+f"(c[0]), "+f"(c[1]), "+f"(c[2]), "+f"(c[3])
        : "r"(a[0]), "r"(a[1]), "r"(a[2]), "r"(a[3]), "r"(b[0]), "r"(b[1]));
}

// ---------------------------------------------------------------------------
// Conversion kernels (elementwise fp16 hi/lo splits)
// ---------------------------------------------------------------------------
__global__ __launch_bounds__(256) void conv_a(const float* __restrict__ src, int use_gc)
{
    int idx = blockIdx.x * 256 + threadIdx.x;
    if (idx < M_ROWS * D_MODEL) {
        float v = use_gc ? g_C[idx] : src[idx];
        __half hi = __float2half(v);
        g_Ahi[idx] = hi;
        g_Alo[idx] = __float2half(v - __half2float(hi));
    }
}
__global__ __launch_bounds__(256) void conv_w(const float* __restrict__ W)
{
    int idx = blockIdx.x * 256 + threadIdx.x;
    if (idx < D_MODEL * D_MODEL) {
        float v = W[idx];
        __half hi = __float2half(v);
        g_Whi[idx] = hi;
        g_Wlo[idx] = __float2half(v - __half2float(hi));
    }
}

// ---------------------------------------------------------------------------
// HMMA GEMM: C[M x 768] = A[M x 768] @ W[768 x 768] + bias via 3-way fp16
// split (A_hi*W_hi + A_lo*W_hi + A_hi*W_lo), fp32 accumulators in registers.
// CTA tile 128x128, 8 warps (4m x 2n), warp tile 32x64, K chunks of 32 halves,
// double-buffered smem, one __syncthreads per chunk.
// ---------------------------------------------------------------------------
#define SA 40     // As row stride (halves): 80B, 16B-aligned, conflict-spread
#define SB 136    // Bs row stride (halves): 272B, 16B-aligned

__global__ __launch_bounds__(256) void hmma_gemm(
    const float* __restrict__ bias, float* __restrict__ Cext, int c_sel)
{
    float* C = (c_sel == 0) ? g_Q : (c_sel == 1) ? g_K : (c_sel == 2) ? g_V : Cext;

    __shared__ __align__(16) __half As[2][128 * SA];   // 2 x 10,240 B
    __shared__ __align__(16) __half Bs[2][32 * SB];    // 2 x  8,704 B

    int tid  = threadIdx.x;
    int warp = tid >> 5;
    int lane = tid & 31;
    int bn = blockIdx.x, bm = blockIdx.y;
    int row0 = bm * 128, col0 = bn * 128;
    int wm = warp >> 1;          // 0..3 -> m offset wm*32
    int wn = warp & 1;           // 0..1 -> n offset wn*64

    float acc[2][8][4];
#pragma unroll
    for (int a = 0; a < 2; a++)
#pragma unroll
        for (int b = 0; b < 8; b++)
#pragma unroll
            for (int c = 0; c < 4; c++) acc[a][b][c] = 0.f;

    const __half* aSeg[3] = {g_Ahi, g_Alo, g_Ahi};
    const __half* bSeg[3] = {g_Whi, g_Whi, g_Wlo};

    // ---- staging-register chunk loaders ----
    uint4 ra0, ra1, rb0, rb1;
    auto ldg_chunk = [&](int seg, int kc0) {
        const __half* aS = aSeg[seg];
        const __half* bS = bSeg[seg];
        // A: 128 rows x 32 halves; 512 16B pieces / 256 threads = 2 each
        int c = tid;
        int row = c >> 2, off = (c & 3) * 8, rg = row0 + row;
        ra0 = (rg < M_ROWS) ? *reinterpret_cast<const uint4*>(aS + (size_t)rg * D_MODEL + kc0 + off)
                            : make_uint4(0u, 0u, 0u, 0u);
        c = tid + 256; row = c >> 2; off = (c & 3) * 8; rg = row0 + row;
        ra1 = (rg < M_ROWS) ? *reinterpret_cast<const uint4*>(aS + (size_t)rg * D_MODEL + kc0 + off)
                            : make_uint4(0u, 0u, 0u, 0u);
        // B: 32 k-rows x 128 halves
        c = tid; row = c >> 4; off = (c & 15) * 8;
        rb0 = *reinterpret_cast<const uint4*>(bS + (size_t)(kc0 + row) * D_MODEL + col0 + off);
        c = tid + 256; row = c >> 4; off = (c & 15) * 8;
        rb1 = *reinterpret_cast<const uint4*>(bS + (size_t)(kc0 + row) * D_MODEL + col0 + off);
    };
    auto sts_chunk = [&](int buf) {
        int c = tid;
        *reinterpret_cast<uint4*>(&As[buf][(c >> 2) * SA + (c & 3) * 8]) = ra0;
        c = tid + 256;
        *reinterpret_cast<uint4*>(&As[buf][(c >> 2) * SA + (c & 3) * 8]) = ra1;
        c = tid;
        *reinterpret_cast<uint4*>(&Bs[buf][(c >> 4) * SB + (c & 15) * 8]) = rb0;
        c = tid + 256;
        *reinterpret_cast<uint4*>(&Bs[buf][(c >> 4) * SB + (c & 15) * 8]) = rb1;
    };

    // Prologue: chunk 0
    ldg_chunk(0, 0);
    sts_chunk(0);
    __syncthreads();

    const int NCH = 3 * (D_MODEL / 32);   // 72
    int cur = 0;
    for (int ch = 0; ch < NCH; ch++) {
        if (ch + 1 < NCH) {
            int nc = ch + 1;
            ldg_chunk(nc / 24, (nc % 24) * 32);
        }

        u32 a_base = smem_u32(As[cur]);
        u32 b_base = smem_u32(Bs[cur]);
#pragma unroll
        for (int kk = 0; kk < 32; kk += 16) {
            u32 af[2][4];
#pragma unroll
            for (int mt = 0; mt < 2; mt++) {
                u32 addr = a_base + 2u * ((wm * 32 + mt * 16 + (lane & 15)) * SA
                                          + kk + (lane >> 4) * 8);
                ldsm_x4(af[mt][0], af[mt][1], af[mt][2], af[mt][3], addr);
            }
            u32 bf[8][2];
#pragma unroll
            for (int p = 0; p < 4; p++) {
                u32 addr = b_base + 2u * ((kk + (lane & 15)) * SB
                                          + wn * 64 + p * 16 + (lane >> 4) * 8);
                u32 r0, r1, r2, r3;
                ldsm_x4_t(r0, r1, r2, r3, addr);
                bf[2 * p][0] = r0;     bf[2 * p][1] = r1;
                bf[2 * p + 1][0] = r2; bf[2 * p + 1][1] = r3;
            }
#pragma unroll
            for (int mt = 0; mt < 2; mt++)
#pragma unroll
                for (int nt = 0; nt < 8; nt++)
                    mma16816(acc[mt][nt], af[mt], bf[nt]);
        }

        if (ch + 1 < NCH) sts_chunk(cur ^ 1);
        __syncthreads();
        cur ^= 1;
    }

    // Epilogue: frag layout c0,c1 -> (row, col..col+1); c2,c3 -> (row+8, ...)
#pragma unroll
    for (int mt = 0; mt < 2; mt++) {
#pragma unroll
        for (int nt = 0; nt < 8; nt++) {
            int row = row0 + wm * 32 + mt * 16 + (lane >> 2);
            int col = col0 + wn * 64 + nt * 8 + (lane & 3) * 2;
            float2 bc = *reinterpret_cast<const float2*>(&bias[col]);
            if (row < M_ROWS) {
                float2 v = make_float2(acc[mt][nt][0] + bc.x, acc[mt][nt][1] + bc.y);
                *reinterpret_cast<float2*>(&C[(size_t)row * D_MODEL + col]) = v;
            }
            if (row + 8 < M_ROWS) {
                float2 v = make_float2(acc[mt][nt][2] + bc.x, acc[mt][nt][3] + bc.y);
                *reinterpret_cast<float2*>(&C[(size_t)(row + 8) * D_MODEL + col]) = v;
            }
        }
    }
}

// ---------------------------------------------------------------------------
// Attention kernel (R8 measured-best, unchanged): grid (B*NH, ATTN_SPLIT).
// K slab transposed in smem; lane-per-candidate; butterfly-order dist^2.
// ---------------------------------------------------------------------------
__global__ __launch_bounds__(256) void attn_kernel(
    const float* __restrict__ log_sigma,
    float* __restrict__ w_out, float* __restrict__ m_out)
{
    extern __shared__ float Ks_t[];             // [DK][L_SEQ] transposed K slab
    __shared__ float q_sh[8][DK];
    __shared__ float w_sh[8][32];
    __shared__ int   c_sh[8][32];

    int bh   = blockIdx.x;
    int b    = bh / NH;
    int h    = bh % NH;
    int tid  = threadIdx.x;
    int warp = tid >> 5;
    int lane = tid & 31;

    float inv = -0.5f * expf(-2.f * log_sigma[0]);   // -0.5 / sigma^2

    const float* kslab = g_K + (size_t)b * L_SEQ * D_MODEL + h * DK;
    for (int idx = tid; idx < L_SEQ * DK; idx += 256) {
        int j = idx >> 6;
        int d = idx & 63;
        Ks_t[d * L_SEQ + j] = kslab[(size_t)j * D_MODEL + d];
    }
    __syncthreads();

    const float* vbase = g_V + (size_t)b * L_SEQ * D_MODEL + h * DK;

    for (int i = blockIdx.y * 8 + warp; i < L_SEQ; i += 8 * ATTN_SPLIT) {
        int rowid = (b * NH + h) * L_SEQ + i;

        const float* qp = g_Q + (size_t)(b * L_SEQ + i) * D_MODEL + h * DK;
        q_sh[warp][lane]      = qp[lane];
        q_sh[warp][lane + 32] = qp[lane + 32];
        __syncwarp();

        float myScore = -INFINITY;
        int   myCol   = 0;
        int   nj;
        bool  act;

        if (i > 0) {
            int p = i - 1, r = p / GRID_SZ, c = p % GRID_SZ;
            int r0 = (r - 2 < 0) ? 0 : r - 2;
            int r1 = (r + 2 > GRID_SZ - 1) ? GRID_SZ - 1 : r + 2;
            int c0 = (c - 2 < 0) ? 0 : c - 2;
            int c1 = (c + 2 > GRID_SZ - 1) ? GRID_SZ - 1 : c + 2;
            int wbox = c1 - c0 + 1;
            int hbox = r1 - r0 + 1;
            nj  = 1 + wbox * hbox;
            act = lane < nj;

            int j = 0;
            if (act && lane > 0) {
                int idx = lane - 1;
                j = 1 + (r0 + idx / wbox) * GRID_SZ + (c0 + idx % wbox);
            }

            if (act) {
                float t[32];
#pragma unroll
                for (int d = 0; d < 32; d++) {
                    float qa = q_sh[warp][d];
                    float ka = Ks_t[d * L_SEQ + j];
                    float qb = q_sh[warp][d + 32];
                    float kb = Ks_t[(d + 32) * L_SEQ + j];
                    float d0 = qa - ka;
                    float d1 = qb - kb;
                    t[d] = fmaf(d1, d1, d0 * d0);
                }
#pragma unroll
                for (int off = 16; off > 0; off >>= 1)
#pragma unroll
                    for (int l = 0; l < 16; l++)
                        if (l < off) t[l] += t[l + off];
                myScore = inv * t[0];
                myCol   = j;
            }
        } else {
            float sc[7];
#pragma unroll
            for (int s = 0; s < 7; s++) {
                int j = s * 32 + lane;
                if (j < L_SEQ) {
                    float acc = 0.f;
#pragma unroll
                    for (int d = 0; d < DK; d++) {
                        float df = q_sh[warp][d] - Ks_t[d * L_SEQ + j];
                        acc = fmaf(df, df, acc);
                    }
                    sc[s] = inv * acc;
                } else {
                    sc[s] = -INFINITY;
                }
            }

            unsigned used = 0;
            for (int t = 0; t < TOPK; t++) {
                float bv = -INFINITY;
                int   bj = 0x7fffffff;
#pragma unroll
                for (int s = 0; s < 7; s++) {
                    if (!((used >> s) & 1u)) {
                        int j = s * 32 + lane;
                        if (sc[s] > bv || (sc[s] == bv && j < bj)) { bv = sc[s]; bj = j; }
                    }
                }
#pragma unroll
                for (int o = 16; o > 0; o >>= 1) {
                    float ov = __shfl_xor_sync(0xffffffffu, bv, o);
                    int   oj = __shfl_xor_sync(0xffffffffu, bj, o);
                    if (ov > bv || (ov == bv && oj < bj)) { bv = ov; bj = oj; }
                }
                if (lane == (bj & 31)) used |= 1u << (bj >> 5);
                if (lane == t) { myScore = bv; myCol = bj; }
            }
            nj  = TOPK;
            act = true;
        }

        float* wrow = w_out + (size_t)rowid * L_SEQ;
        float* mrow = m_out + (size_t)rowid * L_SEQ;
#pragma unroll
        for (int t = lane; t < L_SEQ; t += 32) { wrow[t] = 0.f; mrow[t] = 0.f; }

        float v  = act ? myScore : -INFINITY;
        float mx = v;
#pragma unroll
        for (int o = 16; o > 0; o >>= 1)
            mx = fmaxf(mx, __shfl_xor_sync(0xffffffffu, mx, o));
        float e  = act ? expf(myScore - mx) : 0.f;
        float se = e;
#pragma unroll
        for (int o = 16; o > 0; o >>= 1)
            se += __shfl_xor_sync(0xffffffffu, se, o);
        float w = e / se;

        w_sh[warp][lane] = act ? w : 0.f;
        c_sh[warp][lane] = act ? myCol : 0;
        __syncwarp();

        if (act) {
            wrow[myCol] = w;
            mrow[myCol] = (w > 1e-6f) ? 1.f : 0.f;
        }

        float a0 = 0.f, a1 = 0.f;
#pragma unroll 4
        for (int t = 0; t < nj; t++) {
            float wv  = w_sh[warp][t];
            int   col = c_sh[warp][t];
            const float* vp = vbase + (size_t)col * D_MODEL;
            a0 = fmaf(wv, vp[lane], a0);
            a1 = fmaf(wv, vp[lane + 32], a1);
        }
        float* cp = g_C + (size_t)(b * L_SEQ + i) * D_MODEL + h * DK;
        cp[lane]      = a0;
        cp[lane + 32] = a1;

        __syncwarp();
    }
}

// ---------------------------------------------------------------------------
extern "C" void kernel_launch(void* const* d_in, const int* in_sizes, int n_in,
                              void* d_out, int out_size)
{
    const float* x  = (const float*)d_in[0];
    const float* Wq = (const float*)d_in[1];
    const float* bq = (const float*)d_in[2];
    const float* Wk = (const float*)d_in[3];
    const float* bk = (const float*)d_in[4];
    const float* Wv = (const float*)d_in[5];
    const float* bv = (const float*)d_in[6];
    const float* Wo = (const float*)d_in[7];
    const float* bo = (const float*)d_in[8];
    const float* ls = (const float*)d_in[9];

    float* out   = (float*)d_out;
    float* w_out = out + (size_t)M_ROWS * D_MODEL;
    float* m_out = w_out + (size_t)BATCH * NH * L_SEQ * L_SEQ;

    dim3 ggrid(D_MODEL / 128, (M_ROWS + 127) / 128);          // (6, 50)
    int  ablocks = (M_ROWS * D_MODEL + 255) / 256;             // 18912
    int  wblocks = (D_MODEL * D_MODEL + 255) / 256;            // 2304

    // Split x once; QKV GEMMs share it.
    conv_a<<<ablocks, 256>>>(x, 0);
    conv_w<<<wblocks, 256>>>(Wq);
    hmma_gemm<<<ggrid, 256>>>(bq, nullptr, 0);
    conv_w<<<wblocks, 256>>>(Wk);
    hmma_gemm<<<ggrid, 256>>>(bk, nullptr, 1);
    conv_w<<<wblocks, 256>>>(Wv);
    hmma_gemm<<<ggrid, 256>>>(bv, nullptr, 2);

    // Attention
    const int smem_bytes = L_SEQ * DK * (int)sizeof(float);   // 50432
    cudaFuncSetAttribute(attn_kernel, cudaFuncAttributeMaxDynamicSharedMemorySize,
                         smem_bytes);
    dim3 agrid(BATCH * NH, ATTN_SPLIT);
    attn_kernel<<<agrid, 256, smem_bytes>>>(ls, w_out, m_out);

    // Output projection from g_C
    conv_a<<<ablocks, 256>>>(nullptr, 1);
    conv_w<<<wblocks, 256>>>(Wo);
    hmma_gemm<<<ggrid, 256>>>(bo, out, 3);
}

// round 17
// speedup vs baseline: 1.5968x; 1.0091x over previous
#include <cuda_runtime.h>
#include <cuda_fp16.h>
#include <math.h>

// Problem constants
#define GRID_SZ 14
#define L_SEQ   197           // 14*14 + 1
#define NH      12
#define DK      64
#define D_MODEL 768
#define BATCH   32
#define M_ROWS  (BATCH * L_SEQ)   // 6304
#define TOPK    32
#define N_ROWS_TOT (BATCH * NH * L_SEQ)  // 75648
#define ATTN_SPLIT 4
#define WSZ (D_MODEL * D_MODEL)

typedef unsigned int u32;

// Scratch (device globals: no allocation allowed)
__device__ float g_Q[M_ROWS * D_MODEL];
__device__ float g_K[M_ROWS * D_MODEL];
__device__ float g_V[M_ROWS * D_MODEL];
__device__ float g_C[M_ROWS * D_MODEL];   // consensus (pre-W_o)

// fp16 split operands; all 4 weights pre-split into persistent buffers.
__device__ __half g_Ahi[M_ROWS * D_MODEL];
__device__ __half g_Alo[M_ROWS * D_MODEL];
__device__ __half g_Whi4[4ull * WSZ];
__device__ __half g_Wlo4[4ull * WSZ];

// ---- mma.sync / ldmatrix helpers (plain sm_80-era PTX, no 'a' features) ---
__device__ __forceinline__ u32 smem_u32(const void* p) {
    u32 a;
    asm("{ .reg .u64 t; cvta.to.shared.u64 t, %1; cvt.u32.u64 %0, t; }"
        : "=r"(a) : "l"(p));
    return a;
}
__device__ __forceinline__ void ldsm_x4(u32& r0, u32& r1, u32& r2, u32& r3, u32 addr) {
    asm volatile("ldmatrix.sync.aligned.m8n8.x4.shared.b16 {%0,%1,%2,%3}, [%4];"
                 : "=r"(r0), "=r"(r1), "=r"(r2), "=r"(r3) : "r"(addr));
}
__device__ __forceinline__ void ldsm_x4_t(u32& r0, u32& r1, u32& r2, u32& r3, u32 addr) {
    asm volatile("ldmatrix.sync.aligned.m8n8.x4.trans.shared.b16 {%0,%1,%2,%3}, [%4];"
                 : "=r"(r0), "=r"(r1), "=r"(r2), "=r"(r3) : "r"(addr));
}
__device__ __forceinline__ void mma16816(float* c, const u32* a, const u32* b) {
    asm volatile(
        "mma.sync.aligned.m16n8k16.row.col.f32.f16.f16.f32 "
        "{%0,%1,%2,%3}, {%4,%5,%6,%7}, {%8,%9}, {%0,%1,%2,%3};"
        : "+f"(c[0]), "+f"(c[1]), "+f"(c[2]), "+f"(c[3])
        : "r"(a[0]), "r"(a[1]), "r"(a[2]), "r"(a[3]), "r"(b[0]), "r"(b[1]));
}

// ---------------------------------------------------------------------------
// Conversion kernels
// ---------------------------------------------------------------------------
__global__ __launch_bounds__(256) void conv_a(const float* __restrict__ src, int use_gc)
{
    int idx = blockIdx.x * 256 + threadIdx.x;
    if (idx < M_ROWS * D_MODEL) {
        float v = use_gc ? g_C[idx] : src[idx];
        __half hi = __float2half(v);
        g_Ahi[idx] = hi;
        g_Alo[idx] = __float2half(v - __half2float(hi));
    }
}
// All four weights in one launch: blockIdx.y selects the weight.
__global__ __launch_bounds__(256) void conv_w4(
    const float* __restrict__ W0, const float* __restrict__ W1,
    const float* __restrict__ W2, const float* __restrict__ W3)
{
    int idx = blockIdx.x * 256 + threadIdx.x;
    int wsel = blockIdx.y;
    if (idx < WSZ) {
        const float* W = (wsel == 0) ? W0 : (wsel == 1) ? W1 : (wsel == 2) ? W2 : W3;
        float v = W[idx];
        __half hi = __float2half(v);
        size_t o = (size_t)wsel * WSZ + idx;
        g_Whi4[o] = hi;
        g_Wlo4[o] = __float2half(v - __half2float(hi));
    }
}

// ---------------------------------------------------------------------------
// HMMA GEMM (R13 structure, STATIC smem — the measured-passing config):
// C[M x 768] = A[M x 768] @ W[768 x 768] + bias via 3-way fp16 split
// (A_hi*W_hi + A_lo*W_hi + A_hi*W_lo), fp32 accumulators in registers.
// CTA tile 128x128, 8 warps (4m x 2n), warp tile 32x64, K chunks of 32,
// double-buffered smem, one __syncthreads per chunk (72 chunks).
// Only change vs R13: weight pointers come from persistent g_Whi4/g_Wlo4.
// ---------------------------------------------------------------------------
#define SA 40     // As row stride (halves): 80B
#define SB 136    // Bs row stride (halves): 272B

__global__ __launch_bounds__(256) void hmma_gemm(
    const float* __restrict__ bias, float* __restrict__ Cext, int c_sel, int widx)
{
    float* C = (c_sel == 0) ? g_Q : (c_sel == 1) ? g_K : (c_sel == 2) ? g_V : Cext;
    const __half* Wh = g_Whi4 + (size_t)widx * WSZ;
    const __half* Wl = g_Wlo4 + (size_t)widx * WSZ;

    __shared__ __align__(16) __half As[2][128 * SA];   // 2 x 10,240 B
    __shared__ __align__(16) __half Bs[2][32 * SB];    // 2 x  8,704 B

    int tid  = threadIdx.x;
    int warp = tid >> 5;
    int lane = tid & 31;
    int bn = blockIdx.x, bm = blockIdx.y;
    int row0 = bm * 128, col0 = bn * 128;
    int wm = warp >> 1;          // 0..3 -> m offset wm*32
    int wn = warp & 1;           // 0..1 -> n offset wn*64

    float acc[2][8][4];
#pragma unroll
    for (int a = 0; a < 2; a++)
#pragma unroll
        for (int b = 0; b < 8; b++)
#pragma unroll
            for (int c = 0; c < 4; c++) acc[a][b][c] = 0.f;

    const __half* aSeg[3] = {g_Ahi, g_Alo, g_Ahi};
    const __half* bSeg[3] = {Wh, Wh, Wl};

    // ---- staging-register chunk loaders ----
    uint4 ra0, ra1, rb0, rb1;
    auto ldg_chunk = [&](int seg, int kc0) {
        const __half* aS = aSeg[seg];
        const __half* bS = bSeg[seg];
        // A: 128 rows x 32 halves; 512 16B pieces / 256 threads = 2 each
        int c = tid;
        int row = c >> 2, off = (c & 3) * 8, rg = row0 + row;
        ra0 = (rg < M_ROWS) ? *reinterpret_cast<const uint4*>(aS + (size_t)rg * D_MODEL + kc0 + off)
                            : make_uint4(0u, 0u, 0u, 0u);
        c = tid + 256; row = c >> 2; off = (c & 3) * 8; rg = row0 + row;
        ra1 = (rg < M_ROWS) ? *reinterpret_cast<const uint4*>(aS + (size_t)rg * D_MODEL + kc0 + off)
                            : make_uint4(0u, 0u, 0u, 0u);
        // B: 32 k-rows x 128 halves; piece c -> (c>>4, (c&15)*8)
        c = tid; row = c >> 4; off = (c & 15) * 8;
        rb0 = *reinterpret_cast<const uint4*>(bS + (size_t)(kc0 + row) * D_MODEL + col0 + off);
        c = tid + 256; row = c >> 4; off = (c & 15) * 8;
        rb1 = *reinterpret_cast<const uint4*>(bS + (size_t)(kc0 + row) * D_MODEL + col0 + off);
    };
    auto sts_chunk = [&](int buf) {
        int c = tid;
        *reinterpret_cast<uint4*>(&As[buf][(c >> 2) * SA + (c & 3) * 8]) = ra0;
        c = tid + 256;
        *reinterpret_cast<uint4*>(&As[buf][(c >> 2) * SA + (c & 3) * 8]) = ra1;
        c = tid;
        *reinterpret_cast<uint4*>(&Bs[buf][(c >> 4) * SB + (c & 15) * 8]) = rb0;
        c = tid + 256;
        *reinterpret_cast<uint4*>(&Bs[buf][(c >> 4) * SB + (c & 15) * 8]) = rb1;
    };

    // Prologue: chunk 0
    ldg_chunk(0, 0);
    sts_chunk(0);
    __syncthreads();

    const int NCH = 3 * (D_MODEL / 32);   // 72
    int cur = 0;
    for (int ch = 0; ch < NCH; ch++) {
        if (ch + 1 < NCH) {
            int nc = ch + 1;
            ldg_chunk(nc / 24, (nc % 24) * 32);
        }

        u32 a_base = smem_u32(As[cur]);
        u32 b_base = smem_u32(Bs[cur]);
#pragma unroll
        for (int kk = 0; kk < 32; kk += 16) {
            u32 af[2][4];
#pragma unroll
            for (int mt = 0; mt < 2; mt++) {
                u32 addr = a_base + 2u * ((wm * 32 + mt * 16 + (lane & 15)) * SA
                                          + kk + (lane >> 4) * 8);
                ldsm_x4(af[mt][0], af[mt][1], af[mt][2], af[mt][3], addr);
            }
            u32 bf[8][2];
#pragma unroll
            for (int p = 0; p < 4; p++) {
                u32 addr = b_base + 2u * ((kk + (lane & 15)) * SB
                                          + wn * 64 + p * 16 + (lane >> 4) * 8);
                u32 r0, r1, r2, r3;
                ldsm_x4_t(r0, r1, r2, r3, addr);
                bf[2 * p][0] = r0;     bf[2 * p][1] = r1;
                bf[2 * p + 1][0] = r2; bf[2 * p + 1][1] = r3;
            }
#pragma unroll
            for (int mt = 0; mt < 2; mt++)
#pragma unroll
                for (int nt = 0; nt < 8; nt++)
                    mma16816(acc[mt][nt], af[mt], bf[nt]);
        }

        if (ch + 1 < NCH) sts_chunk(cur ^ 1);
        __syncthreads();
        cur ^= 1;
    }

    // Epilogue: frag layout c0,c1 -> (row, col..col+1); c2,c3 -> (row+8, ...)
#pragma unroll
    for (int mt = 0; mt < 2; mt++) {
#pragma unroll
        for (int nt = 0; nt < 8; nt++) {
            int row = row0 + wm * 32 + mt * 16 + (lane >> 2);
            int col = col0 + wn * 64 + nt * 8 + (lane & 3) * 2;
            float2 bc = *reinterpret_cast<const float2*>(&bias[col]);
            if (row < M_ROWS) {
                float2 v = make_float2(acc[mt][nt][0] + bc.x, acc[mt][nt][1] + bc.y);
                *reinterpret_cast<float2*>(&C[(size_t)row * D_MODEL + col]) = v;
            }
            if (row + 8 < M_ROWS) {
                float2 v = make_float2(acc[mt][nt][2] + bc.x, acc[mt][nt][3] + bc.y);
                *reinterpret_cast<float2*>(&C[(size_t)(row + 8) * D_MODEL + col]) = v;
            }
        }
    }
}

// ---------------------------------------------------------------------------
// Attention kernel (R8 measured-best, unchanged): grid (B*NH, ATTN_SPLIT).
// K slab transposed in smem; lane-per-candidate; butterfly-order dist^2.
// ---------------------------------------------------------------------------
__global__ __launch_bounds__(256) void attn_kernel(
    const float* __restrict__ log_sigma,
    float* __restrict__ w_out, float* __restrict__ m_out)
{
    extern __shared__ float Ks_t[];             // [DK][L_SEQ] transposed K slab
    __shared__ float q_sh[8][DK];
    __shared__ float w_sh[8][32];
    __shared__ int   c_sh[8][32];

    int bh   = blockIdx.x;
    int b    = bh / NH;
    int h    = bh % NH;
    int tid  = threadIdx.x;
    int warp = tid >> 5;
    int lane = tid & 31;

    float inv = -0.5f * expf(-2.f * log_sigma[0]);   // -0.5 / sigma^2

    const float* kslab = g_K + (size_t)b * L_SEQ * D_MODEL + h * DK;
    for (int idx = tid; idx < L_SEQ * DK; idx += 256) {
        int j = idx >> 6;
        int d = idx & 63;
        Ks_t[d * L_SEQ + j] = kslab[(size_t)j * D_MODEL + d];
    }
    __syncthreads();

    const float* vbase = g_V + (size_t)b * L_SEQ * D_MODEL + h * DK;

    for (int i = blockIdx.y * 8 + warp; i < L_SEQ; i += 8 * ATTN_SPLIT) {
        int rowid = (b * NH + h) * L_SEQ + i;

        const float* qp = g_Q + (size_t)(b * L_SEQ + i) * D_MODEL + h * DK;
        q_sh[warp][lane]      = qp[lane];
        q_sh[warp][lane + 32] = qp[lane + 32];
        __syncwarp();

        float myScore = -INFINITY;
        int   myCol   = 0;
        int   nj;
        bool  act;

        if (i > 0) {
            int p = i - 1, r = p / GRID_SZ, c = p % GRID_SZ;
            int r0 = (r - 2 < 0) ? 0 : r - 2;
            int r1 = (r + 2 > GRID_SZ - 1) ? GRID_SZ - 1 : r + 2;
            int c0 = (c - 2 < 0) ? 0 : c - 2;
            int c1 = (c + 2 > GRID_SZ - 1) ? GRID_SZ - 1 : c + 2;
            int wbox = c1 - c0 + 1;
            int hbox = r1 - r0 + 1;
            nj  = 1 + wbox * hbox;
            act = lane < nj;

            int j = 0;
            if (act && lane > 0) {
                int idx = lane - 1;
                j = 1 + (r0 + idx / wbox) * GRID_SZ + (c0 + idx % wbox);
            }

            if (act) {
                float t[32];
#pragma unroll
                for (int d = 0; d < 32; d++) {
                    float qa = q_sh[warp][d];
                    float ka = Ks_t[d * L_SEQ + j];
                    float qb = q_sh[warp][d + 32];
                    float kb = Ks_t[(d + 32) * L_SEQ + j];
                    float d0 = qa - ka;
                    float d1 = qb - kb;
                    t[d] = fmaf(d1, d1, d0 * d0);
                }
#pragma unroll
                for (int off = 16; off > 0; off >>= 1)
#pragma unroll
                    for (int l = 0; l < 16; l++)
                        if (l < off) t[l] += t[l + off];
                myScore = inv * t[0];
                myCol   = j;
            }
        } else {
            float sc[7];
#pragma unroll
            for (int s = 0; s < 7; s++) {
                int j = s * 32 + lane;
                if (j < L_SEQ) {
                    float acc = 0.f;
#pragma unroll
                    for (int d = 0; d < DK; d++) {
                        float df = q_sh[warp][d] - Ks_t[d * L_SEQ + j];
                        acc = fmaf(df, df, acc);
                    }
                    sc[s] = inv * acc;
                } else {
                    sc[s] = -INFINITY;
                }
            }

            unsigned used = 0;
            for (int t = 0; t < TOPK; t++) {
                float bv = -INFINITY;
                int   bj = 0x7fffffff;
#pragma unroll
                for (int s = 0; s < 7; s++) {
                    if (!((used >> s) & 1u)) {
                        int j = s * 32 + lane;
                        if (sc[s] > bv || (sc[s] == bv && j < bj)) { bv = sc[s]; bj = j; }
                    }
                }
#pragma unroll
                for (int o = 16; o > 0; o >>= 1) {
                    float ov = __shfl_xor_sync(0xffffffffu, bv, o);
                    int   oj = __shfl_xor_sync(0xffffffffu, bj, o);
                    if (ov > bv || (ov == bv && oj < bj)) { bv = ov; bj = oj; }
                }
                if (lane == (bj & 31)) used |= 1u << (bj >> 5);
                if (lane == t) { myScore = bv; myCol = bj; }
            }
            nj  = TOPK;
            act = true;
        }

        float* wrow = w_out + (size_t)rowid * L_SEQ;
        float* mrow = m_out + (size_t)rowid * L_SEQ;
#pragma unroll
        for (int t = lane; t < L_SEQ; t += 32) { wrow[t] = 0.f; mrow[t] = 0.f; }

        float v  = act ? myScore : -INFINITY;
        float mx = v;
#pragma unroll
        for (int o = 16; o > 0; o >>= 1)
            mx = fmaxf(mx, __shfl_xor_sync(0xffffffffu, mx, o));
        float e  = act ? expf(myScore - mx) : 0.f;
        float se = e;
#pragma unroll
        for (int o = 16; o > 0; o >>= 1)
            se += __shfl_xor_sync(0xffffffffu, se, o);
        float w = e / se;

        w_sh[warp][lane] = act ? w : 0.f;
        c_sh[warp][lane] = act ? myCol : 0;
        __syncwarp();

        if (act) {
            wrow[myCol] = w;
            mrow[myCol] = (w > 1e-6f) ? 1.f : 0.f;
        }

        float a0 = 0.f, a1 = 0.f;
#pragma unroll 4
        for (int t = 0; t < nj; t++) {
            float wv  = w_sh[warp][t];
            int   col = c_sh[warp][t];
            const float* vp = vbase + (size_t)col * D_MODEL;
            a0 = fmaf(wv, vp[lane], a0);
            a1 = fmaf(wv, vp[lane + 32], a1);
        }
        float* cp = g_C + (size_t)(b * L_SEQ + i) * D_MODEL + h * DK;
        cp[lane]      = a0;
        cp[lane + 32] = a1;

        __syncwarp();
    }
}

// ---------------------------------------------------------------------------
extern "C" void kernel_launch(void* const* d_in, const int* in_sizes, int n_in,
                              void* d_out, int out_size)
{
    const float* x  = (const float*)d_in[0];
    const float* Wq = (const float*)d_in[1];
    const float* bq = (const float*)d_in[2];
    const float* Wk = (const float*)d_in[3];
    const float* bk = (const float*)d_in[4];
    const float* Wv = (const float*)d_in[5];
    const float* bv = (const float*)d_in[6];
    const float* Wo = (const float*)d_in[7];
    const float* bo = (const float*)d_in[8];
    const float* ls = (const float*)d_in[9];

    float* out   = (float*)d_out;
    float* w_out = out + (size_t)M_ROWS * D_MODEL;
    float* m_out = w_out + (size_t)BATCH * NH * L_SEQ * L_SEQ;

    dim3 ggrid(D_MODEL / 128, (M_ROWS + 127) / 128);          // (6, 50)
    int  ablocks = (M_ROWS * D_MODEL + 255) / 256;             // 18912
    dim3 wgrid((WSZ + 255) / 256, 4);                          // all 4 weights

    // Convert inputs once
    conv_a<<<ablocks, 256>>>(x, 0);
    conv_w4<<<wgrid, 256>>>(Wq, Wk, Wv, Wo);

    // QKV projections
    hmma_gemm<<<ggrid, 256>>>(bq, nullptr, 0, 0);
    hmma_gemm<<<ggrid, 256>>>(bk, nullptr, 1, 1);
    hmma_gemm<<<ggrid, 256>>>(bv, nullptr, 2, 2);

    // Attention
    const int smem_bytes = L_SEQ * DK * (int)sizeof(float);   // 50432
    cudaFuncSetAttribute(attn_kernel, cudaFuncAttributeMaxDynamicSharedMemorySize,
                         smem_bytes);
    dim3 agrid(BATCH * NH, ATTN_SPLIT);
    attn_kernel<<<agrid, 256, smem_bytes>>>(ls, w_out, m_out);

    // Output projection from g_C
    conv_a<<<ablocks, 256>>>(nullptr, 1);
    hmma_gemm<<<ggrid, 256>>>(bo, out, 3, 3);
}